// round 5
// baseline (speedup 1.0000x reference)
#include <cuda_runtime.h>
#include <cuda_bf16.h>

// Problem constants
#define NB 256   // batch (both i and j axes)
#define ND 64    // dim_z
#define NS 32    // samples
#define NPOINTS_PER_D (NB * NS)          // 8192 (j,s) points per dim d
#define P 4                              // points per thread
#define THREADS 128
#define POINTS_PER_BLOCK (THREADS * P)   // 512
#define YTILES (NPOINTS_PER_D / POINTS_PER_BLOCK) // 16

// Hybrid split: NB_MUFU posteriors via ex2.approx (MUFU pipe),
// NB_POLY via FMA-pipe polynomial exp2. Interleaved 3:1 in the loop body.
#define NB_POLY 64
#define NB_MUFU (NB - NB_POLY)           // 192

typedef unsigned long long u64;

__device__ __forceinline__ float ex2_approx(float x) {
    float r;
    asm("ex2.approx.ftz.f32 %0, %1;" : "=f"(r) : "f"(x));
    return r;
}

// ---- packed f32x2 helpers ----
__device__ __forceinline__ u64 pk2(float lo, float hi) {
    u64 r; asm("mov.b64 %0, {%1,%2};" : "=l"(r) : "f"(lo), "f"(hi)); return r;
}
__device__ __forceinline__ void upk2(u64 v, float& lo, float& hi) {
    asm("mov.b64 {%0,%1}, %2;" : "=f"(lo), "=f"(hi) : "l"(v));
}
__device__ __forceinline__ u64 fma2_(u64 a, u64 b, u64 c) {
    u64 r; asm("fma.rn.f32x2 %0, %1, %2, %3;" : "=l"(r) : "l"(a), "l"(b), "l"(c)); return r;
}
__device__ __forceinline__ u64 add2_(u64 a, u64 b) {
    u64 r; asm("add.rn.f32x2 %0, %1, %2;" : "=l"(r) : "l"(a), "l"(b)); return r;
}

__global__ void zero_out_kernel(float* out) { out[0] = 0.0f; }

__global__ __launch_bounds__(THREADS, 8)
void kl_kernel(const float* __restrict__ prior_mean,
               const float* __restrict__ prior_logvar,
               const float* __restrict__ post_mean,
               const float* __restrict__ post_logvar,
               const float* __restrict__ eps,
               float* __restrict__ out)
{
    constexpr float LOG_2PI  = 1.8378770664093453f;
    constexpr float INV_LN2  = 1.4426950408889634f;
    constexpr float LOG_B    = 5.545177444479562f;   // ln(256)
    constexpr float VAR_EPS  = 1.0e-4f;

    // Coefficients replicated pairwise so the inner loop loads packed f32x2
    // operands directly: sm[i*8 + {0..5}] = {a,a,b,b,c,c} (stride 32B, aligned).
    __shared__ __align__(16) float sm[NB * 8];
    __shared__ float sm_red[THREADS / 32];

    const int d = blockIdx.x;
    const int t = threadIdx.x;

    // Per-posterior-i quadratic coefficients in base-2 domain:
    //   w_i(z) = a*z^2 + b*z + c,  a=-inv, b=2*inv*m, c=c0-inv*m^2
#pragma unroll
    for (int r = 0; r < NB / THREADS; r++) {
        int i = t + r * THREADS;
        float m   = post_mean[i * ND + d];
        float lv  = post_logvar[i * ND + d];
        float inv = INV_LN2 / (2.0f * __expf(lv) + VAR_EPS);
        float c0  = (-0.5f * LOG_2PI - 0.5f * lv) * INV_LN2;
        float a = -inv;
        float b = 2.0f * inv * m;
        float c = fmaf(-inv, m * m, c0);
        sm[i * 8 + 0] = a; sm[i * 8 + 1] = a;
        sm[i * 8 + 2] = b; sm[i * 8 + 3] = b;
        sm[i * 8 + 4] = c; sm[i * 8 + 5] = c;
        sm[i * 8 + 6] = 0.0f; sm[i * 8 + 7] = 0.0f;
    }
    __syncthreads();

    // Each thread owns P=4 sample points (j,s) for this d.
    const int qbase = blockIdx.y * POINTS_PER_BLOCK + t;

    float z[P], acc[P];
#pragma unroll
    for (int p = 0; p < P; p++) {
        int q = qbase + p * THREADS;
        int j = q >> 5;
        int s = q & 31;
        float pmj  = post_mean[j * ND + d];
        float plvj = post_logvar[j * ND + d];
        float e    = eps[(j * ND + d) * NS + s];
        z[p]   = fmaf(e, __expf(0.5f * plvj), pmj);
        acc[p] = 0.0f;
    }
    const u64 z01 = pk2(z[0], z[1]);
    const u64 z23 = pk2(z[2], z[3]);

    // Packed constants (hoisted, loop-invariant).
    const u64 MAGIC2  = pk2(12582912.0f, 12582912.0f);    // 1.5*2^23, RN round-to-int
    const u64 NMAGIC2 = pk2(-12582912.0f, -12582912.0f);
    const u64 MONE2   = pk2(-1.0f, -1.0f);
    const u64 ONE2    = pk2(1.0f, 1.0f);
    const u64 C1_2    = pk2(0.6931471806f, 0.6931471806f);
    const u64 C2_2    = pk2(0.2402265070f, 0.2402265070f);
    const u64 C3_2    = pk2(0.0555041087f, 0.0555041087f);

    // Main loop: sum_i 2^{w_i(z_p)}, unstabilized single pass (safe: w<=1.6,
    // diagonal term keeps sum >= ~e^-14). Interleave 3 MUFU-i with 1 poly-i
    // per block so MUFU/FMA/ALU pipes overlap inside each warp.
#pragma unroll 2
    for (int ib = 0; ib < NB_POLY; ib++) {
        // --- 3 posteriors via MUFU ex2 ---
#pragma unroll
        for (int r = 0; r < 3; r++) {
            int i = ib * 3 + r;
            ulonglong2 ab = *(const ulonglong2*)(sm + i * 8);   // (a,a) (b,b)
            u64 c2v       = *(const u64*)(sm + i * 8 + 4);       // (c,c)
            u64 t01 = fma2_(z01, ab.x, ab.y);
            u64 w01 = fma2_(z01, t01, c2v);
            u64 t23 = fma2_(z23, ab.x, ab.y);
            u64 w23 = fma2_(z23, t23, c2v);
            float w0, w1, w2, w3;
            upk2(w01, w0, w1);
            upk2(w23, w2, w3);
            acc[0] += ex2_approx(w0);
            acc[1] += ex2_approx(w1);
            acc[2] += ex2_approx(w2);
            acc[3] += ex2_approx(w3);
        }
        // --- 1 posterior via FMA-pipe exp2 ---
        {
            int i = NB_MUFU + ib;
            ulonglong2 ab = *(const ulonglong2*)(sm + i * 8);
            u64 c2v       = *(const u64*)(sm + i * 8 + 4);
            u64 t01 = fma2_(z01, ab.x, ab.y);
            u64 w01 = fma2_(z01, t01, c2v);
            u64 t23 = fma2_(z23, ab.x, ab.y);
            u64 w23 = fma2_(z23, t23, c2v);

#pragma unroll
            for (int h = 0; h < 2; h++) {
                u64 wp = h ? w23 : w01;
                // clamp so the exponent splice stays in normal-float range;
                // clamped terms contribute <= 2^-123 ~ 1e-37, invisible vs
                // the sum's floor ~e^-14.
                float wa, wb;
                upk2(wp, wa, wb);
                wa = fmaxf(wa, -124.0f);
                wb = fmaxf(wb, -124.0f);
                u64 wc = pk2(wa, wb);
                u64 tt = add2_(wc, MAGIC2);        // bits: 0x4B400000 + k (k=round(w))
                u64 kf = add2_(tt, NMAGIC2);       // k as float
                u64 f  = fma2_(kf, MONE2, wc);     // f = wc - k, in [-0.5, 0.5]
                u64 q  = fma2_(f, C3_2, C2_2);     // cubic Taylor for 2^f
                q = fma2_(f, q, C1_2);
                q = fma2_(f, q, ONE2);
                float t0, t1, p0, p1;
                upk2(tt, t0, t1);
                upk2(q,  p0, p1);
                int sb0 = __float_as_int(t0) << 23;   // == k0 << 23 (magic high bits vanish)
                int sb1 = __float_as_int(t1) << 23;
                // 2^w = p * 2^k via exponent add (p in [0.70,1.42], normal result)
                acc[2 * h + 0] += __int_as_float(__float_as_int(p0) + sb0);
                acc[2 * h + 1] += __int_as_float(__float_as_int(p1) + sb1);
            }
        }
    }

    // Epilogue: lse, prior log-density, density gap.
    float local = 0.0f;
#pragma unroll
    for (int p = 0; p < P; p++) {
        int q = qbase + p * THREADS;
        int j = q >> 5;
        float lse = __logf(acc[p]);   // ln(sum 2^w) = ln(sum e^v)

        float pm  = prior_mean[j * ND + d];
        float plv = prior_logvar[j * ND + d];
        float dd  = z[p] - pm;
        float logprior = -0.5f * LOG_2PI - 0.5f * plv
                         - dd * dd / (2.0f * __expf(plv) + VAR_EPS);

        local += (lse - LOG_B) - logprior;
    }

    // Block reduction -> atomicAdd, scaled by 1/(B*S).
#pragma unroll
    for (int off = 16; off > 0; off >>= 1)
        local += __shfl_xor_sync(0xffffffffu, local, off);

    int lane = t & 31, warp = t >> 5;
    if (lane == 0) sm_red[warp] = local;
    __syncthreads();
    if (warp == 0) {
        float v = (lane < THREADS / 32) ? sm_red[lane] : 0.0f;
#pragma unroll
        for (int off = 2; off > 0; off >>= 1)
            v += __shfl_xor_sync(0xffffffffu, v, off);
        if (lane == 0)
            atomicAdd(out, v * (1.0f / (float)(NB * NS)));
    }
}

extern "C" void kernel_launch(void* const* d_in, const int* in_sizes, int n_in,
                              void* d_out, int out_size) {
    const float* prior_mean   = (const float*)d_in[0];
    const float* prior_logvar = (const float*)d_in[1];
    const float* post_mean    = (const float*)d_in[2];
    const float* post_logvar  = (const float*)d_in[3];
    const float* eps          = (const float*)d_in[4];
    float* out = (float*)d_out;

    zero_out_kernel<<<1, 1>>>(out);
    dim3 grid(ND, YTILES);
    kl_kernel<<<grid, THREADS>>>(prior_mean, prior_logvar, post_mean,
                                 post_logvar, eps, out);
}